// round 1
// baseline (speedup 1.0000x reference)
#include <cuda_runtime.h>
#include <math.h>

// Problem constants (from reference): B=256, T=512, C=512, L=64
#define BN 256
#define TN 512
#define CN 512
#define LN 64
#define SN (2 * LN + 1)   // 129 states
#define BLANK (CN - 1)    // 511
#define NEGV (-1e30f)
#define EPSV (1e-7f)
#define NTHREADS 160      // 5 warps >= SN

// CTC forward (alpha) DP in log space, one block per batch element,
// one thread per extended-label state. Double-buffered alpha in smem,
// one __syncthreads per time step. Probability for step t+1 is prefetched
// before the barrier so the gather latency overlaps compute + barrier.
__global__ __launch_bounds__(NTHREADS, 8)
void ctc_forward_kernel(const int* __restrict__ labels,     // [B, L]
                        const float* __restrict__ y_pred,   // [B, T, C]
                        const int* __restrict__ in_len,     // [B, 1]
                        const int* __restrict__ lab_len,    // [B, 1]
                        float* __restrict__ out)            // [B, 1]
{
    const int b = blockIdx.x;
    const int s = threadIdx.x;
    const bool act = (s < SN);

    __shared__ int   ext[SN];
    __shared__ float alpha[2][SN + 2];   // +2 front padding so [s] is state s-2
    __shared__ float fin[SN];

    // Build extended label sequence: even -> blank, odd -> labels[s/2]
    if (act) {
        int cls = (s & 1) ? labels[b * LN + (s >> 1)] : BLANK;
        ext[s] = cls;
    }
    // Padding entries (indices 0,1 of each buffer) are permanently NEG
    if (s < 2) {
        alpha[0][s] = NEGV;
        alpha[1][s] = NEGV;
    }
    __syncthreads();

    int  cls = act ? ext[s] : 0;
    bool alw = false;
    if (act && s >= 2) {
        int c2 = ext[s - 2];
        alw = (cls != BLANK) && (cls != c2);
    }

    const float* base = y_pred + (size_t)b * TN * CN;
    const int T_eff = in_len[b];

    // t = 0: alpha0[s] = emit(0,s) for s<2, else NEG
    float p_cur  = act ? base[cls] : 1.0f;
    float p_next = act ? base[CN + cls] : 1.0f;   // prefetch t=1 (TN >= 2)

    float a = NEGV;
    if (act) {
        float e0 = logf(p_cur + EPSV);
        a = (s < 2) ? e0 : NEGV;
        alpha[0][s + 2] = a;
    }
    if (act && T_eff == 1) fin[s] = a;
    __syncthreads();

    int cur = 0;
    #pragma unroll 4
    for (int t = 1; t < TN; ++t) {
        float p = p_next;
        // Prefetch next step's probability (gather) — hidden behind compute+barrier
        if (t + 1 < TN && act) p_next = base[(size_t)(t + 1) * CN + cls];

        float newv = NEGV;
        if (act) {
            float a0 = alpha[cur][s + 2];
            float a1 = alpha[cur][s + 1];
            float a2 = alw ? alpha[cur][s] : NEGV;
            float m  = fmaxf(a0, fmaxf(a1, a2));
            float sum = expf(a0 - m) + expf(a1 - m) + expf(a2 - m);
            newv = m + logf(sum) + logf(p + EPSV);
            alpha[cur ^ 1][s + 2] = newv;
        }
        cur ^= 1;
        __syncthreads();
        if (act && t == T_eff - 1) fin[s] = newv;
    }
    __syncthreads();

    if (s == 0) {
        int ll = lab_len[b];
        int i1 = 2 * ll;
        int i2 = 2 * ll - 1;
        // jnp negative index wraps; clamp generically (here ll=64 always)
        if (i1 < 0) i1 += SN;
        if (i2 < 0) i2 += SN;
        float x1 = fin[i1];
        float x2 = fin[i2];
        float m = fmaxf(x1, x2);
        out[b] = -(m + logf(expf(x1 - m) + expf(x2 - m)));
    }
}

extern "C" void kernel_launch(void* const* d_in, const int* in_sizes, int n_in,
                              void* d_out, int out_size)
{
    const int*   y_true       = (const int*)d_in[0];   // [B, L] int32
    const float* y_pred       = (const float*)d_in[1]; // [B, T, C] f32
    const int*   input_length = (const int*)d_in[2];   // [B, 1] int32
    const int*   label_length = (const int*)d_in[3];   // [B, 1] int32
    float*       out          = (float*)d_out;         // [B, 1] f32

    ctc_forward_kernel<<<BN, NTHREADS>>>(y_true, y_pred, input_length, label_length, out);
}

// round 2
// speedup vs baseline: 1.0685x; 1.0685x over previous
#include <cuda_runtime.h>
#include <math.h>

// B=256, T=512, C=512, L=64
#define BN 256
#define TN 512
#define CN 512
#define LN 64
#define SN (2 * LN + 1)     // 129 states
#define BLANK (CN - 1)      // 511
#define EPSV (1e-7f)
#define NTH 160             // 5 full warps
#define PF 8                // prefetch depth (independent LDGs in flight)
#define LN2F 0.6931471805599453f

// CTC forward DP in LINEAR probability space with exact power-of-2
// renormalization. Identical math to log-space logsumexp recursion:
//   alpha_t[s] = (alpha[s] + alpha[s-1] + allow*alpha[s-2]) * (p + eps)
// Each step multiplies by 2^9 (exact) for range; every 8 steps the max's
// binary exponent is extracted (REDUX.MAX over uint-ordered nonneg floats)
// and folded into the next step. Exponent bookkeeping is integer-exact.
__global__ __launch_bounds__(NTH, 8)
void ctc_lin_kernel(const int* __restrict__ labels,     // [B, L]
                    const float* __restrict__ y_pred,   // [B, T, C]
                    const int* __restrict__ in_len,     // [B, 1]
                    const int* __restrict__ lab_len,    // [B, 1]
                    float* __restrict__ out)            // [B, 1]
{
    const int b = blockIdx.x;
    const int s = threadIdx.x;
    const bool act = (s < SN);
    const int warp = s >> 5;

    __shared__ int      ext[SN];
    __shared__ float    alpha[2][SN + 2];   // +2 front pad: [s] is state s-2
    __shared__ float    fin[SN];
    __shared__ unsigned pmax[5];
    __shared__ int      ecap;

    if (act) {
        int c = (s & 1) ? labels[b * LN + (s >> 1)] : BLANK;
        ext[s] = c;
    }
    if (s < 2) { alpha[0][s] = 0.0f; alpha[1][s] = 0.0f; }
    __syncthreads();

    const int  cls = act ? ext[s] : BLANK;
    bool alw = false;
    if (act && s >= 2) {
        int c2 = ext[s - 2];
        alw = (cls != BLANK) && (cls != c2);
    }

    const float* base = y_pred + (size_t)b * TN * CN;
    const int T_eff = in_len[b];

    // t = 0 : alpha0[s] = p + eps for s < 2, else 0
    float a0v = 0.0f;
    if (act) {
        float p0 = base[cls];
        a0v = (s < 2) ? (p0 + EPSV) : 0.0f;
        alpha[0][s + 2] = a0v;
    }
    if (T_eff == 1) {
        if (act) fin[s] = a0v;
        if (s == 0) ecap = 0;
    }

    // Prefetch pe = (p + eps) * 512 for t = 1..PF (single-rounded fma; x512 exact)
    float pebuf[PF];
    #pragma unroll
    for (int i = 0; i < PF; ++i) {
        pebuf[i] = act ? fmaf(base[(size_t)(1 + i) * CN + cls], 512.0f, 512.0f * EPSV)
                       : 0.0f;
    }
    __syncthreads();

    int   cur = 0;
    int   E = 0;            // applied exponent sum (uniform across threads)
    int   pend_e = 0;       // exponent extracted, to be applied next step
    float pend_sc = 1.0f;

    #pragma unroll 8
    for (int t = 1; t < TN; ++t) {
        const int slot = (t - 1) & (PF - 1);
        float pe = pebuf[slot];
        if (act && (t + PF) < TN)
            pebuf[slot] = fmaf(base[(size_t)(t + PF) * CN + cls], 512.0f, 512.0f * EPSV);

        // Apply pending renorm scale (uniform) and account it
        pe *= pend_sc;
        E += pend_e;
        pend_e = 0; pend_sc = 1.0f;

        float nv = 0.0f;
        if (act) {
            float a0 = alpha[cur][s + 2];
            float a1 = alpha[cur][s + 1];
            float a2 = alw ? alpha[cur][s] : 0.0f;
            nv = (a0 + a1 + a2) * pe;
            alpha[cur ^ 1][s + 2] = nv;
        }
        cur ^= 1;
        __syncthreads();

        if ((t & 7) == 0) {
            // Max over states; nonneg floats order as uints -> REDUX.MAX
            unsigned u = __float_as_uint(act ? nv : 0.0f);
            u = __reduce_max_sync(0xffffffffu, u);
            if ((threadIdx.x & 31) == 0) pmax[warp] = u;
            __syncthreads();
            unsigned m = pmax[0];
            m = max(m, pmax[1]); m = max(m, pmax[2]);
            m = max(m, pmax[3]); m = max(m, pmax[4]);
            // floor exponent of normal float
            int e = (int)(m >> 23) - 127;
            pend_e  = e;
            pend_sc = __uint_as_float((unsigned)(127 - e) << 23);  // 2^-e exact
        }

        if (t == T_eff - 1) {
            if (act) fin[s] = nv;
            if (s == 0) ecap = E;
        }
    }
    __syncthreads();

    if (s == 0) {
        int ll = lab_len[b];
        int i1 = 2 * ll;
        int i2 = 2 * ll - 1;
        if (i1 < 0) i1 += SN;
        if (i2 < 0) i2 += SN;
        float x = fin[i1] + fin[i2];
        // stored = true * 2^(9*(T_eff-1)) * 2^(-ecap)
        // loss = -log(true) = -log(stored) + (9*(T_eff-1) - ecap) * ln2
        out[b] = -logf(x) + ((float)(9 * (T_eff - 1) - ecap)) * LN2F;
    }
}

extern "C" void kernel_launch(void* const* d_in, const int* in_sizes, int n_in,
                              void* d_out, int out_size)
{
    const int*   y_true       = (const int*)d_in[0];
    const float* y_pred       = (const float*)d_in[1];
    const int*   input_length = (const int*)d_in[2];
    const int*   label_length = (const int*)d_in[3];
    float*       out          = (float*)d_out;

    ctc_lin_kernel<<<BN, NTH>>>(y_true, y_pred, input_length, label_length, out);
}

// round 3
// speedup vs baseline: 3.8754x; 3.6270x over previous
#include <cuda_runtime.h>
#include <math.h>

// B=256, T=512, C=512, L=64
#define BN 256
#define TN 512
#define CN 512
#define LN 64
#define SN (2 * LN + 1)     // 129 states
#define BLANK (CN - 1)      // 511
#define EPSV (1e-7f)
#define PF 8                // pipeline depth (stages)
#define HTH 160             // threads per batch-half (5 warps)
#define NTH (2 * HTH)       // 320 threads, 2 batch elements per CTA
#define LN2F 0.6931471805599453f

// CTC forward DP, linear space + exact power-of-2 renorm (same math as
// log-space logsumexp). Two batch elements per CTA (independent chains,
// shared barrier). Probability rows streamed into smem via an 8-deep
// cp.async pipeline (coalesced), states gather from smem.
__global__ __launch_bounds__(NTH, 1)
void ctc_pipe_kernel(const int* __restrict__ labels,     // [B, L]
                     const float* __restrict__ y_pred,   // [B, T, C]
                     const int* __restrict__ in_len,     // [B, 1]
                     const int* __restrict__ lab_len,    // [B, 1]
                     float* __restrict__ out)            // [B, 1]
{
    const int tid  = threadIdx.x;
    const int half = tid / HTH;          // warps 0-4 -> half 0, 5-9 -> half 1
    const int hs   = tid % HTH;          // state index within half
    const bool act = (hs < SN);
    const int warp = tid >> 5;           // 0..9
    const int b    = blockIdx.x * 2 + half;

    __shared__ __align__(16) float pbuf[2][PF][CN];   // 32KB row pipeline
    __shared__ float    alpha[2][2][SN + 2];
    __shared__ float    fin[2][SN];
    __shared__ int      ext[2][SN];
    __shared__ unsigned pmax[10];
    __shared__ int      ecap[2];

    if (act)
        ext[half][hs] = (hs & 1) ? labels[b * LN + (hs >> 1)] : BLANK;
    if (hs < 2) { alpha[half][0][hs] = 0.0f; alpha[half][1][hs] = 0.0f; }
    __syncthreads();

    const int cls = act ? ext[half][hs] : 0;
    bool alw = false;
    if (act && hs >= 2) {
        int c2 = ext[half][hs - 2];
        alw = (cls != BLANK) && (cls != c2);
    }

    const float* base  = y_pred + (size_t)b * TN * CN;
    const int    T_eff = in_len[b];

    // t = 0
    float a0v = 0.0f;
    if (act) {
        float p0 = base[cls];
        a0v = (hs < 2) ? (p0 + EPSV) : 0.0f;
        alpha[half][0][hs + 2] = a0v;
    }
    if (T_eff == 1) {
        if (act) fin[half][hs] = a0v;
        if (hs == 0) ecap[half] = 0;
    }

    // --- cp.async row-copy helper (threads 0..255 move 4KB = 2 rows) ---
    const int  cp_h    = tid >> 7;           // 0 or 1 (for tid < 256)
    const int  cp_lane = tid & 127;          // 16B chunk index within row
    const bool cp_act  = (tid < 256);
    const float* cp_src_base =
        y_pred + ((size_t)(blockIdx.x * 2 + cp_h) * TN) * CN + cp_lane * 4;

    // Prologue: stages 1..PF-1, one group each
    #pragma unroll
    for (int st = 1; st < PF; ++st) {
        if (cp_act) {
            unsigned dst = (unsigned)__cvta_generic_to_shared(
                &pbuf[cp_h][st & (PF - 1)][cp_lane * 4]);
            const float* src = cp_src_base + (size_t)st * CN;
            asm volatile("cp.async.cg.shared.global [%0], [%1], 16;"
                         :: "r"(dst), "l"(src));
        }
        asm volatile("cp.async.commit_group;");
    }

    int   cur = 0;
    int   E = 0;
    int   pend_e = 0;
    float pend_sc = 1.0f;

    #pragma unroll 8
    for (int t = 1; t < TN; ++t) {
        // stage t complete after leaving <= PF-2 groups pending
        asm volatile("cp.async.wait_group %0;" :: "n"(PF - 2));
        __syncthreads();   // publishes alpha[t-1], stage-t row, frees slot (t-1)%PF

        // refill: stage t+PF-1 -> slot (t-1)%PF (consumed last step)
        {
            int st = t + PF - 1;
            if (cp_act && st < TN) {
                unsigned dst = (unsigned)__cvta_generic_to_shared(
                    &pbuf[cp_h][st & (PF - 1)][cp_lane * 4]);
                const float* src = cp_src_base + (size_t)st * CN;
                asm volatile("cp.async.cg.shared.global [%0], [%1], 16;"
                             :: "r"(dst), "l"(src));
            }
            asm volatile("cp.async.commit_group;");
        }

        // apply pending renorm (uniform per half)
        float sc512  = 512.0f * pend_sc;
        float epssc  = (512.0f * EPSV) * pend_sc;
        E += pend_e;
        pend_e = 0; pend_sc = 1.0f;

        float nv = 0.0f;
        if (act) {
            float p  = pbuf[half][t & (PF - 1)][cls];
            float a0 = alpha[half][cur][hs + 2];
            float a1 = alpha[half][cur][hs + 1];
            float a2 = alw ? alpha[half][cur][hs] : 0.0f;
            nv = (a0 + a1 + a2) * fmaf(p, sc512, epssc);
            alpha[half][cur ^ 1][hs + 2] = nv;
        }
        cur ^= 1;

        if ((t & 7) == 0) {
            // per-half max via warp reduce (nonneg floats order as uints)
            unsigned u = __float_as_uint(act ? nv : 0.0f);
            u = __reduce_max_sync(0xffffffffu, u);
            if ((tid & 31) == 0) pmax[warp] = u;
            __syncthreads();
            int w0 = half * 5;
            unsigned m = pmax[w0];
            m = max(m, pmax[w0 + 1]); m = max(m, pmax[w0 + 2]);
            m = max(m, pmax[w0 + 3]); m = max(m, pmax[w0 + 4]);
            int e = (int)(m >> 23) - 127;
            pend_e  = e;
            pend_sc = __uint_as_float((unsigned)(127 - e) << 23);  // 2^-e
        }

        if (t == T_eff - 1) {
            if (act) fin[half][hs] = nv;
            if (hs == 0) ecap[half] = E;
        }
    }
    __syncthreads();

    if (hs == 0) {
        int ll = lab_len[b];
        int i1 = 2 * ll;
        int i2 = 2 * ll - 1;
        if (i1 < 0) i1 += SN;
        if (i2 < 0) i2 += SN;
        float x = fin[half][i1] + fin[half][i2];
        // stored = true * 2^(9*(T_eff-1) - ecap)
        out[b] = -logf(x) + ((float)(9 * (T_eff - 1) - ecap[half])) * LN2F;
    }
}

extern "C" void kernel_launch(void* const* d_in, const int* in_sizes, int n_in,
                              void* d_out, int out_size)
{
    const int*   y_true       = (const int*)d_in[0];
    const float* y_pred       = (const float*)d_in[1];
    const int*   input_length = (const int*)d_in[2];
    const int*   label_length = (const int*)d_in[3];
    float*       out          = (float*)d_out;

    ctc_pipe_kernel<<<BN / 2, NTH>>>(y_true, y_pred, input_length, label_length, out);
}

// round 4
// speedup vs baseline: 4.6674x; 1.2044x over previous
#include <cuda_runtime.h>
#include <math.h>

// B=256, T=512, C=512, L=64
#define BN 256
#define TN 512
#define CN 512
#define LN 64
#define SN 129              // 2L+1
#define BLANK 511
#define EPSV 1e-7f
#define RS 8                // row-ring slots (cp.async pipeline depth)
#define KS 5                // states per lane (32*5 >= 129)
#define LN2F 0.6931471805599453f
#define FULL 0xffffffffu

// CTC forward DP: one WARP per batch element. Alpha states live in
// registers (5/lane); s-1/s-2 neighbors via shfl_up. The warp streams its
// own probability rows through an 8-slot smem ring with cp.async — the
// only per-step syncs are cp.async.wait_group + one __syncwarp.
// Linear-space recursion with exact power-of-2 renorm (identical math and
// operation order to the previous log-equivalent kernel).
__global__ __launch_bounds__(32, 8)
void ctc_warp_kernel(const int* __restrict__ labels,     // [B, L]
                     const float* __restrict__ y_pred,   // [B, T, C]
                     const int* __restrict__ in_len,     // [B, 1]
                     const int* __restrict__ lab_len,    // [B, 1]
                     float* __restrict__ out)            // [B, 1]
{
    const int b    = blockIdx.x;
    const int lane = threadIdx.x;

    __shared__ __align__(16) float rows[RS][CN];   // 16KB ring
    __shared__ float fin[SN];
    __shared__ int   ecap_sh;

    // Extended labels: state s = KS*lane + j ; even -> blank, odd -> label
    int  cls[KS];
    bool valid[KS];
    #pragma unroll
    for (int j = 0; j < KS; ++j) {
        int s = KS * lane + j;
        valid[j] = (s < SN);
        int c = BLANK;
        if (valid[j] && (s & 1)) c = labels[b * LN + (s >> 1)];
        cls[j] = valid[j] ? c : 0;        // class 0 keeps loads in-bounds
    }
    // cls[s-2] for j=0 (lane-1 slot 3) and j=1 (lane-1 slot 4)
    int cu2 = __shfl_up_sync(FULL, cls[KS - 2], 1);
    int cu1 = __shfl_up_sync(FULL, cls[KS - 1], 1);
    bool alw[KS];
    #pragma unroll
    for (int j = 0; j < KS; ++j) {
        int s   = KS * lane + j;
        int cm2 = (j >= 2) ? cls[j - 2] : ((j == 1) ? cu1 : cu2);
        alw[j] = valid[j] && (s >= 2) && (cls[j] != BLANK) && (cls[j] != cm2);
    }

    const float* base  = y_pred + (size_t)b * TN * CN;
    const int    T_eff = in_len[b];

    // t = 0 : alpha0[s] = p + eps for s < 2, else 0  (invalid pinned 0)
    float a[KS];
    #pragma unroll
    for (int j = 0; j < KS; ++j) {
        int s = KS * lane + j;
        a[j] = (s < 2) ? (base[cls[j]] + EPSV) : 0.0f;
    }
    if (T_eff == 1) {
        #pragma unroll
        for (int j = 0; j < KS; ++j)
            if (valid[j]) fin[KS * lane + j] = a[j];
        if (lane == 0) ecap_sh = 0;
    }

    // Prologue: fill ring with rows t = 1 .. RS-1 (one commit group each).
    // Each lane moves 4 x 16B chunks: floats [lane*4 + k*128 .. +3].
    #pragma unroll
    for (int st = 1; st < RS; ++st) {
        #pragma unroll
        for (int k = 0; k < 4; ++k) {
            unsigned dst = (unsigned)__cvta_generic_to_shared(
                &rows[st & (RS - 1)][lane * 4 + k * 128]);
            const float* src = base + (size_t)st * CN + lane * 4 + k * 128;
            asm volatile("cp.async.cg.shared.global [%0], [%1], 16;"
                         :: "r"(dst), "l"(src));
        }
        asm volatile("cp.async.commit_group;");
    }

    int   E = 0, pend_e = 0;
    float pend_sc = 1.0f;

    #pragma unroll 8
    for (int t = 1; t < TN; ++t) {
        asm volatile("cp.async.wait_group %0;" :: "n"(RS - 2)); // row t done
        __syncwarp();                                           // cross-lane vis

        const float* row = rows[t & (RS - 1)];
        float sc512 = 512.0f * pend_sc;
        float epssc = (512.0f * EPSV) * pend_sc;
        E += pend_e; pend_e = 0; pend_sc = 1.0f;

        // Gather pe = (p + eps) * 512 * pend_sc from smem (invalid -> 0)
        float pe[KS];
        #pragma unroll
        for (int j = 0; j < KS; ++j)
            pe[j] = valid[j] ? fmaf(row[cls[j]], sc512, epssc) : 0.0f;

        // Refill slot (t-1)&7 with row t+7 (safe: LDS above issued first,
        // warp-convergent; async write lands far later anyway)
        {
            int st = t + RS - 1;
            if (st < TN) {
                #pragma unroll
                for (int k = 0; k < 4; ++k) {
                    unsigned dst = (unsigned)__cvta_generic_to_shared(
                        &rows[st & (RS - 1)][lane * 4 + k * 128]);
                    const float* src = base + (size_t)st * CN + lane * 4 + k * 128;
                    asm volatile("cp.async.cg.shared.global [%0], [%1], 16;"
                                 :: "r"(dst), "l"(src));
                }
            }
            asm volatile("cp.async.commit_group;");  // unconditional: keep count
        }

        // Halo from lane below: old a[s-1], a[s-2] for this lane's j=0
        float h1 = __shfl_up_sync(FULL, a[KS - 1], 1);
        float h2 = __shfl_up_sync(FULL, a[KS - 2], 1);
        if (lane == 0) { h1 = 0.0f; h2 = 0.0f; }

        float n0 = (a[0] + h1   + (alw[0] ? h2   : 0.0f)) * pe[0];
        float n1 = (a[1] + a[0] + (alw[1] ? h1   : 0.0f)) * pe[1];
        float n2 = (a[2] + a[1] + (alw[2] ? a[0] : 0.0f)) * pe[2];
        float n3 = (a[3] + a[2] + (alw[3] ? a[1] : 0.0f)) * pe[3];
        float n4 = (a[4] + a[3] + (alw[4] ? a[2] : 0.0f)) * pe[4];
        a[0] = n0; a[1] = n1; a[2] = n2; a[3] = n3; a[4] = n4;

        if ((t & 7) == 0) {
            // warp-wide max (nonneg floats order as uints) -> exact 2^-e renorm
            unsigned u = __float_as_uint(a[0]);
            u = max(u, __float_as_uint(a[1]));
            u = max(u, __float_as_uint(a[2]));
            u = max(u, __float_as_uint(a[3]));
            u = max(u, __float_as_uint(a[4]));
            u = __reduce_max_sync(FULL, u);
            int e = (int)(u >> 23) - 127;
            pend_e  = e;
            pend_sc = __uint_as_float((unsigned)(127 - e) << 23);  // 2^-e
        }

        if (t == T_eff - 1) {
            #pragma unroll
            for (int j = 0; j < KS; ++j)
                if (valid[j]) fin[KS * lane + j] = a[j];
            if (lane == 0) ecap_sh = E;
        }
    }
    __syncwarp();

    if (lane == 0) {
        int ll = lab_len[b];
        int i1 = 2 * ll;
        int i2 = 2 * ll - 1;
        if (i1 < 0) i1 += SN;
        if (i2 < 0) i2 += SN;
        float x = fin[i1] + fin[i2];
        // stored = true * 2^(9*(T_eff-1) - ecap)
        out[b] = -logf(x) + ((float)(9 * (T_eff - 1) - ecap_sh)) * LN2F;
    }
}

extern "C" void kernel_launch(void* const* d_in, const int* in_sizes, int n_in,
                              void* d_out, int out_size)
{
    const int*   y_true       = (const int*)d_in[0];
    const float* y_pred       = (const float*)d_in[1];
    const int*   input_length = (const int*)d_in[2];
    const int*   label_length = (const int*)d_in[3];
    float*       out          = (float*)d_out;

    ctc_warp_kernel<<<BN, 32>>>(y_true, y_pred, input_length, label_length, out);
}